// round 7
// baseline (speedup 1.0000x reference)
#include <cuda_runtime.h>
#include <cstdint>

#define N_TOK 4096
#define D_DIM 1024
#define TOPK 128
#define G_CTAS 128
#define T_THREADS 256
#define NWARPS (T_THREADS / 32)            // 8
#define ROWS_PER_CTA (N_TOK / G_CTAS)      // 32
#define RPW (ROWS_PER_CTA / NWARPS)        // 4
#define NEG_MASK_F (-1e30f)

// ---------------- persistent device scratch (no allocations) ----------------
__device__ __align__(16) float g_xn[(size_t)N_TOK * D_DIM];   // normalized features (16 MB)
__device__ __align__(16) float g_cisT[(size_t)N_TOK * TOPK];  // cis transposed [n][t] (2 MB)
__device__ float g_rel[N_TOK];
// one 128B line per (step, cta) slot: polls spread across LTS slices
__device__ __align__(128) unsigned long long g_best[TOPK][G_CTAS][16];  // 2 MB
__device__ float g_attmin[G_CTAS];
__device__ float g_attmax[G_CTAS];
__device__ unsigned int g_bar_cnt = 0;                        // sense-reversing barrier
__device__ unsigned int g_bar_gen = 0;

// Order-preserving float->u32 key; low word = inverted index so on equal keys
// the SMALLEST index wins (matches jnp.argmax first-occurrence).
__device__ __forceinline__ unsigned long long pack_key(float v, int idx) {
    unsigned b = __float_as_uint(v);
    unsigned key = (b & 0x80000000u) ? ~b : (b | 0x80000000u);
    return ((unsigned long long)key << 32) | (unsigned)(0xFFFFFFFFu - (unsigned)idx);
}

__device__ __forceinline__ unsigned long long ld_acq(const unsigned long long* p) {
    unsigned long long v;
    asm volatile("ld.global.acquire.gpu.u64 %0, [%1];" : "=l"(v) : "l"(p));
    return v;
}
__device__ __forceinline__ void st_rel(unsigned long long* p, unsigned long long v) {
    asm volatile("st.global.release.gpu.u64 [%0], %1;" :: "l"(p), "l"(v) : "memory");
}

__global__ void __launch_bounds__(T_THREADS, 1)
cdpruner_kernel(const float* __restrict__ IF, const float* __restrict__ ATT,
                float* __restrict__ OUT)
{
    const int g    = blockIdx.x;
    const int tid  = threadIdx.x;
    const int warp = tid >> 5;
    const int lane = tid & 31;
    const int n0   = g * ROWS_PER_CTA;

    __shared__ float s_mm[2];
    __shared__ unsigned long long s_red[4];
    __shared__ unsigned long long s_best[NWARPS];
    __shared__ float s_cis[ROWS_PER_CTA][TOPK];       // 16 KB, own rows' cis
    __shared__ __align__(16) float s_xj[D_DIM];       // 4 KB, staged xn[j]
    __shared__ __align__(16) float s_cj[TOPK];        // 512 B, staged cisT[j]
    __shared__ int s_js[TOPK];

    // ---------------- Phase A ----------------
    // zero this CTA's slot column (one padded line per step)
    if (tid < TOPK) g_best[tid][g][0] = 0ULL;

    // attention min/max partials for this CTA's 32 tokens
    if (warp == 0) {
        float v = ATT[n0 + lane];
        float vmin = v, vmax = v;
        #pragma unroll
        for (int off = 16; off; off >>= 1) {
            vmin = fminf(vmin, __shfl_xor_sync(0xFFFFFFFFu, vmin, off));
            vmax = fmaxf(vmax, __shfl_xor_sync(0xFFFFFFFFu, vmax, off));
        }
        if (lane == 0) { g_attmin[g] = vmin; g_attmax[g] = vmax; }
    }

    // Normalize rows; KEEP the normalized slice in registers (xr); write g_xn
    // for cross-CTA row-j reads. Arithmetic order identical to passing rounds.
    float4 xr[RPW][8];
    float  dd_r[RPW];
    #pragma unroll
    for (int r = 0; r < RPW; r++) {
        const int n = n0 + warp * RPW + r;
        const float4* xp = (const float4*)(IF + (size_t)n * D_DIM);
        float ss = 0.f;
        #pragma unroll
        for (int u = 0; u < 8; u++) {
            xr[r][u] = xp[u * 32 + lane];
            ss = fmaf(xr[r][u].x, xr[r][u].x, ss);
            ss = fmaf(xr[r][u].y, xr[r][u].y, ss);
            ss = fmaf(xr[r][u].z, xr[r][u].z, ss);
            ss = fmaf(xr[r][u].w, xr[r][u].w, ss);
        }
        #pragma unroll
        for (int off = 16; off; off >>= 1) ss += __shfl_xor_sync(0xFFFFFFFFu, ss, off);
        const float norm = __fsqrt_rn(ss);
        float dd = 0.f;
        float4* op = (float4*)(g_xn + (size_t)n * D_DIM);
        #pragma unroll
        for (int u = 0; u < 8; u++) {
            float4 o;
            o.x = __fdiv_rn(xr[r][u].x, norm);
            o.y = __fdiv_rn(xr[r][u].y, norm);
            o.z = __fdiv_rn(xr[r][u].z, norm);
            o.w = __fdiv_rn(xr[r][u].w, norm);
            dd = fmaf(o.x, o.x, dd);
            dd = fmaf(o.y, o.y, dd);
            dd = fmaf(o.z, o.z, dd);
            dd = fmaf(o.w, o.w, dd);
            xr[r][u] = o;
            op[u * 32 + lane] = o;
        }
        #pragma unroll
        for (int off = 16; off; off >>= 1) dd += __shfl_xor_sync(0xFFFFFFFFu, dd, off);
        dd_r[r] = dd;
    }

    // ---- sense-reversing grid barrier ----
    __syncthreads();
    if (tid == 0) {
        __threadfence();
        unsigned gen = *(volatile unsigned*)&g_bar_gen;
        if (atomicAdd(&g_bar_cnt, 1u) == G_CTAS - 1) {
            g_bar_cnt = 0u;
            __threadfence();
            atomicAdd(&g_bar_gen, 1u);
        } else {
            while (*(volatile unsigned*)&g_bar_gen == gen) { }
        }
        __threadfence();
    }
    __syncthreads();

    // global attention min/max (redundant per CTA)
    if (warp == 0) {
        float vmin = g_attmin[lane], vmax = g_attmax[lane];
        #pragma unroll
        for (int k = 1; k < G_CTAS / 32; k++) {
            vmin = fminf(vmin, g_attmin[lane + 32 * k]);
            vmax = fmaxf(vmax, g_attmax[lane + 32 * k]);
        }
        #pragma unroll
        for (int off = 16; off; off >>= 1) {
            vmin = fminf(vmin, __shfl_xor_sync(0xFFFFFFFFu, vmin, off));
            vmax = fmaxf(vmax, __shfl_xor_sync(0xFFFFFFFFu, vmax, off));
        }
        if (lane == 0) { s_mm[0] = vmin; s_mm[1] = vmax; }
    }
    __syncthreads();

    // rel + initial di2s per owned row (lane-uniform registers)
    const float rmin  = -s_mm[1];
    const float rmax  = -s_mm[0];
    const float denom = __fsub_rn(rmax, rmin);
    float rel_r[RPW], d_r[RPW];
    {
        unsigned long long wbest = 0ULL;
        #pragma unroll
        for (int r = 0; r < RPW; r++) {
            const int n = n0 + warp * RPW + r;
            const float relv = __fdiv_rn(__fadd_rn(__fsub_rn(-ATT[n], rmin), 1e-6f), denom);
            rel_r[r] = relv;
            if (lane == 0) g_rel[n] = relv;
            const float dval = __fmul_rn(__fmul_rn(relv, dd_r[r]), relv);
            d_r[r] = dval;
            const unsigned long long p = pack_key(dval, n);
            if (p > wbest) wbest = p;
        }
        if (lane == 0) s_best[warp] = wbest;
    }
    __syncthreads();
    if (tid == 0) {
        unsigned long long b = s_best[0];
        #pragma unroll
        for (int k = 1; k < NWARPS; k++) if (s_best[k] > b) b = s_best[k];
        st_rel(&g_best[0][g][0], b);              // publish step-0 candidate
    }

    // ---------------- Phase B: 128 greedy steps, slot-based sync ----------------
    for (int i = 0; i < TOPK; i++) {
        // wait for all 128 CTAs' step-i candidates; block-reduce the winner
        if (tid < G_CTAS) {
            const unsigned long long* slot = &g_best[i][tid][0];
            unsigned long long bb;
            do { bb = ld_acq(slot); } while (bb == 0ULL);
            #pragma unroll
            for (int off = 16; off; off >>= 1) {
                unsigned long long q = __shfl_xor_sync(0xFFFFFFFFu, bb, off);
                if (q > bb) bb = q;
            }
            if (lane == 0) s_red[warp] = bb;
        }
        __syncthreads();
        unsigned long long w = s_red[0];
        #pragma unroll
        for (int k = 1; k < 4; k++) if (s_red[k] > w) w = s_red[k];
        const unsigned key  = (unsigned)(w >> 32);
        const unsigned bits = (key & 0x80000000u) ? (key ^ 0x80000000u) : ~key;
        const float dj = __uint_as_float(bits);
        int j = (int)(0xFFFFFFFFu - (unsigned)(w & 0xFFFFFFFFu));
        j = (j < 0) ? 0 : ((j > N_TOK - 1) ? N_TOK - 1 : j);   // defensive clamp
        if (tid == 0) s_js[i] = j;                 // output copied after the loop

        if (i == TOPK - 1) break;

        const float sqj  = __fsqrt_rn(dj);
        const float relj = __ldg(&g_rel[j]);

        // stage winner-row data through smem ONCE per CTA:
        //   xn[j] (4 KB): 256 threads x one float4 each
        //   cisT[j] (512 B): warp 0, one float4 per lane (stale tail masked at use)
        ((float4*)s_xj)[tid] = ((const float4*)(g_xn + (size_t)j * D_DIM))[tid];
        if (warp == 0)
            ((float4*)s_cj)[lane] = ((const float4*)(g_cisT + (size_t)j * TOPK))[lane];
        __syncthreads();

        // per-warp cj registers from smem (masked to t < i)
        float cj[4];
        #pragma unroll
        for (int u = 0; u < 4; u++) {
            const int t = lane + 32 * u;
            cj[u] = (t < i) ? s_cj[t] : 0.f;
        }

        const float4* xjs = (const float4*)s_xj;
        unsigned long long wbest = 0ULL;
        #pragma unroll
        for (int r = 0; r < RPW; r++) {
            const int n     = n0 + warp * RPW + r;
            const int row_l = warp * RPW + r;
            float dp = 0.f;                         // register-resident dot
            #pragma unroll
            for (int u = 0; u < 8; u++) {
                const float4 xj = xjs[u * 32 + lane];
                dp = fmaf(xj.x, xr[r][u].x, dp);
                dp = fmaf(xj.y, xr[r][u].y, dp);
                dp = fmaf(xj.z, xr[r][u].z, dp);
                dp = fmaf(xj.w, xr[r][u].w, dp);
            }
            float pp = 0.f;                         // projection over t < i
            #pragma unroll
            for (int u = 0; u < 4; u++) {
                const int t = lane + 32 * u;
                if (t < i) pp = fmaf(cj[u], s_cis[row_l][t], pp);
            }
            #pragma unroll
            for (int off = 16; off; off >>= 1) {
                dp += __shfl_xor_sync(0xFFFFFFFFu, dp, off);
                pp += __shfl_xor_sync(0xFFFFFFFFu, pp, off);
            }
            const float kjn = __fmul_rn(__fmul_rn(relj, dp), rel_r[r]);
            const float e   = __fdiv_rn(__fsub_rn(kjn, pp), sqj);
            if (lane == 0) {
                s_cis[row_l][i] = e;
                g_cisT[(size_t)n * TOPK + i] = e;
            }
            float d = __fsub_rn(d_r[r], __fmul_rn(e, e));
            if (n == j) d = NEG_MASK_F;
            d_r[r] = d;
            const unsigned long long p = pack_key(d, n);
            if (p > wbest) wbest = p;
        }
        if (lane == 0) s_best[warp] = wbest;
        __syncthreads();
        if (tid == 0) {
            unsigned long long b = s_best[0];
            #pragma unroll
            for (int k = 1; k < NWARPS; k++) if (s_best[k] > b) b = s_best[k];
            st_rel(&g_best[i + 1][g][0], b);       // release covers cis stores
        }
    }

    // ---------------- OUT copy (off the critical loop) ----------------
    __syncthreads();
    const int jj = s_js[g];                        // CTA g copies output row g
    ((float4*)(OUT + (size_t)g * D_DIM))[tid] =
        ((const float4*)(IF + (size_t)jj * D_DIM))[tid];
}

extern "C" void kernel_launch(void* const* d_in, const int* in_sizes, int n_in,
                              void* d_out, int out_size) {
    const float* IF  = (const float*)d_in[0];   // image_features (1,4096,1024) f32
    const float* ATT = (const float*)d_in[1];   // attention (1,4096) f32
    float* OUT = (float*)d_out;                 // (128, 1024) f32
    (void)in_sizes; (void)n_in; (void)out_size;
    cdpruner_kernel<<<G_CTAS, T_THREADS>>>(IF, ATT, OUT);
}

// round 8
// speedup vs baseline: 1.0738x; 1.0738x over previous
#include <cuda_runtime.h>
#include <cstdint>

#define N_TOK 4096
#define D_DIM 1024
#define TOPK 128
#define G_CTAS 128
#define T_THREADS 256
#define NWARPS (T_THREADS / 32)            // 8
#define ROWS_PER_CTA (N_TOK / G_CTAS)      // 32
#define RPW (ROWS_PER_CTA / NWARPS)        // 4
#define NEG_MASK_F (-1e30f)

// ---------------- persistent device scratch (no allocations) ----------------
__device__ __align__(16) float g_xn[(size_t)N_TOK * D_DIM];   // normalized features (16 MB)
__device__ __align__(16) float g_cisT[(size_t)N_TOK * TOPK];  // cis transposed [n][t] (2 MB)
__device__ float g_rel[N_TOK];
// one 128B line per (step, cta) slot: polls spread across LTS slices
__device__ __align__(128) unsigned long long g_best[TOPK][G_CTAS][16];  // 2 MB
__device__ float g_attmin[G_CTAS];
__device__ float g_attmax[G_CTAS];
__device__ unsigned int g_bar_cnt = 0;                        // sense-reversing barrier
__device__ unsigned int g_bar_gen = 0;

// Order-preserving float->u32 key; low word = inverted index so on equal keys
// the SMALLEST index wins (matches jnp.argmax first-occurrence).
__device__ __forceinline__ unsigned long long pack_key(float v, int idx) {
    unsigned b = __float_as_uint(v);
    unsigned key = (b & 0x80000000u) ? ~b : (b | 0x80000000u);
    return ((unsigned long long)key << 32) | (unsigned)(0xFFFFFFFFu - (unsigned)idx);
}

__device__ __forceinline__ unsigned long long ld_acq(const unsigned long long* p) {
    unsigned long long v;
    asm volatile("ld.global.acquire.gpu.u64 %0, [%1];" : "=l"(v) : "l"(p));
    return v;
}
__device__ __forceinline__ void st_rel(unsigned long long* p, unsigned long long v) {
    asm volatile("st.global.release.gpu.u64 [%0], %1;" :: "l"(p), "l"(v) : "memory");
}

__global__ void __launch_bounds__(T_THREADS, 1)
cdpruner_kernel(const float* __restrict__ IF, const float* __restrict__ ATT,
                float* __restrict__ OUT)
{
    const int g    = blockIdx.x;
    const int tid  = threadIdx.x;
    const int warp = tid >> 5;
    const int lane = tid & 31;
    const int n0   = g * ROWS_PER_CTA;

    __shared__ float s_mm[2];
    __shared__ unsigned long long s_red[4];
    __shared__ unsigned long long s_best[NWARPS];
    __shared__ float s_cis[ROWS_PER_CTA][TOPK];   // 16 KB, own rows' cis
    __shared__ int s_js[TOPK];

    // ---------------- Phase A ----------------
    if (tid < TOPK) g_best[tid][g][0] = 0ULL;     // zero this CTA's slot column

    if (warp == 0) {                              // attention min/max partials
        float v = ATT[n0 + lane];
        float vmin = v, vmax = v;
        #pragma unroll
        for (int off = 16; off; off >>= 1) {
            vmin = fminf(vmin, __shfl_xor_sync(0xFFFFFFFFu, vmin, off));
            vmax = fmaxf(vmax, __shfl_xor_sync(0xFFFFFFFFu, vmax, off));
        }
        if (lane == 0) { g_attmin[g] = vmin; g_attmax[g] = vmax; }
    }

    // Normalize rows; KEEP the normalized slice in registers (xr); write g_xn
    // for cross-CTA row-j reads.
    float4 xr[RPW][8];
    float  dd_r[RPW];
    #pragma unroll
    for (int r = 0; r < RPW; r++) {
        const int n = n0 + warp * RPW + r;
        const float4* xp = (const float4*)(IF + (size_t)n * D_DIM);
        float ss = 0.f;
        #pragma unroll
        for (int u = 0; u < 8; u++) {
            xr[r][u] = xp[u * 32 + lane];
            ss = fmaf(xr[r][u].x, xr[r][u].x, ss);
            ss = fmaf(xr[r][u].y, xr[r][u].y, ss);
            ss = fmaf(xr[r][u].z, xr[r][u].z, ss);
            ss = fmaf(xr[r][u].w, xr[r][u].w, ss);
        }
        #pragma unroll
        for (int off = 16; off; off >>= 1) ss += __shfl_xor_sync(0xFFFFFFFFu, ss, off);
        const float norm = __fsqrt_rn(ss);
        float dd = 0.f;
        float4* op = (float4*)(g_xn + (size_t)n * D_DIM);
        #pragma unroll
        for (int u = 0; u < 8; u++) {
            float4 o;
            o.x = __fdiv_rn(xr[r][u].x, norm);
            o.y = __fdiv_rn(xr[r][u].y, norm);
            o.z = __fdiv_rn(xr[r][u].z, norm);
            o.w = __fdiv_rn(xr[r][u].w, norm);
            dd = fmaf(o.x, o.x, dd);
            dd = fmaf(o.y, o.y, dd);
            dd = fmaf(o.z, o.z, dd);
            dd = fmaf(o.w, o.w, dd);
            xr[r][u] = o;
            op[u * 32 + lane] = o;
        }
        #pragma unroll
        for (int off = 16; off; off >>= 1) dd += __shfl_xor_sync(0xFFFFFFFFu, dd, off);
        dd_r[r] = dd;
    }

    // ---- sense-reversing grid barrier ----
    __syncthreads();
    if (tid == 0) {
        __threadfence();
        unsigned gen = *(volatile unsigned*)&g_bar_gen;
        if (atomicAdd(&g_bar_cnt, 1u) == G_CTAS - 1) {
            g_bar_cnt = 0u;
            __threadfence();
            atomicAdd(&g_bar_gen, 1u);
        } else {
            while (*(volatile unsigned*)&g_bar_gen == gen) { }
        }
        __threadfence();
    }
    __syncthreads();

    // global attention min/max (redundant per CTA)
    if (warp == 0) {
        float vmin = g_attmin[lane], vmax = g_attmax[lane];
        #pragma unroll
        for (int k = 1; k < G_CTAS / 32; k++) {
            vmin = fminf(vmin, g_attmin[lane + 32 * k]);
            vmax = fmaxf(vmax, g_attmax[lane + 32 * k]);
        }
        #pragma unroll
        for (int off = 16; off; off >>= 1) {
            vmin = fminf(vmin, __shfl_xor_sync(0xFFFFFFFFu, vmin, off));
            vmax = fmaxf(vmax, __shfl_xor_sync(0xFFFFFFFFu, vmax, off));
        }
        if (lane == 0) { s_mm[0] = vmin; s_mm[1] = vmax; }
    }
    __syncthreads();

    // rel + initial di2s per owned row
    const float rmin  = -s_mm[1];
    const float rmax  = -s_mm[0];
    const float denom = __fsub_rn(rmax, rmin);
    float rel_r[RPW], d_r[RPW];
    {
        unsigned long long wbest = 0ULL;
        #pragma unroll
        for (int r = 0; r < RPW; r++) {
            const int n = n0 + warp * RPW + r;
            const float relv = __fdiv_rn(__fadd_rn(__fsub_rn(-ATT[n], rmin), 1e-6f), denom);
            rel_r[r] = relv;
            if (lane == 0) g_rel[n] = relv;
            const float dval = __fmul_rn(__fmul_rn(relv, dd_r[r]), relv);
            d_r[r] = dval;
            const unsigned long long p = pack_key(dval, n);
            if (p > wbest) wbest = p;
        }
        if (lane == 0) s_best[warp] = wbest;
    }
    __syncthreads();
    if (warp == 0) {                              // warp-0 shuffle reduce + publish
        unsigned long long bb = s_best[lane & (NWARPS - 1)];
        #pragma unroll
        for (int off = 4; off; off >>= 1) {
            unsigned long long q = __shfl_xor_sync(0xFFFFFFFFu, bb, off);
            if (q > bb) bb = q;
        }
        if (lane == 0) st_rel(&g_best[0][g][0], bb);
    }

    // ---------------- Phase B: 128 greedy steps ----------------
    for (int i = 0; i < TOPK; i++) {
        // wait for all 128 CTAs' step-i candidates; block-reduce the winner
        if (tid < G_CTAS) {
            const unsigned long long* slot = &g_best[i][tid][0];
            unsigned long long bb;
            do { bb = ld_acq(slot); } while (bb == 0ULL);
            #pragma unroll
            for (int off = 16; off; off >>= 1) {
                unsigned long long q = __shfl_xor_sync(0xFFFFFFFFu, bb, off);
                if (q > bb) bb = q;
            }
            if (lane == 0) s_red[warp] = bb;
        }
        __syncthreads();
        unsigned long long w = s_red[0];
        #pragma unroll
        for (int k = 1; k < 4; k++) if (s_red[k] > w) w = s_red[k];
        const unsigned key  = (unsigned)(w >> 32);
        const unsigned bits = (key & 0x80000000u) ? (key ^ 0x80000000u) : ~key;
        const float dj = __uint_as_float(bits);
        int j = (int)(0xFFFFFFFFu - (unsigned)(w & 0xFFFFFFFFu));
        j = (j < 0) ? 0 : ((j > N_TOK - 1) ? N_TOK - 1 : j);   // defensive clamp
        if (tid == 0) s_js[i] = j;                 // output copied after the loop

        if (i == TOPK - 1) break;

        const float sqj  = __fsqrt_rn(dj);
        const float relj = __ldg(&g_rel[j]);

        // per-warp register loads of xn[j] and cisT[j] (no cross-warp coupling)
        const float4* xjp = (const float4*)(g_xn + (size_t)j * D_DIM);
        float4 xj[8];
        #pragma unroll
        for (int u = 0; u < 8; u++) xj[u] = xjp[u * 32 + lane];
        float cj[4];
        #pragma unroll
        for (int u = 0; u < 4; u++) {
            const int t = lane + 32 * u;
            cj[u] = (t < i) ? __ldg(&g_cisT[(size_t)j * TOPK + t]) : 0.f;
        }

        // 4-row-interleaved dot (independent FMA chains)
        float dp[RPW] = {0.f, 0.f, 0.f, 0.f};
        #pragma unroll
        for (int u = 0; u < 8; u++) {
            #pragma unroll
            for (int r = 0; r < RPW; r++) {
                dp[r] = fmaf(xj[u].x, xr[r][u].x, dp[r]);
                dp[r] = fmaf(xj[u].y, xr[r][u].y, dp[r]);
                dp[r] = fmaf(xj[u].z, xr[r][u].z, dp[r]);
                dp[r] = fmaf(xj[u].w, xr[r][u].w, dp[r]);
            }
        }

        // projection + fuse into single reduction value per row:
        // num_lane = scale*dp_lane - pp_lane, with scale = relj*rel_n
        float num[RPW];
        #pragma unroll
        for (int r = 0; r < RPW; r++) {
            const int row_l = warp * RPW + r;
            float pp = 0.f;
            #pragma unroll
            for (int u = 0; u < 4; u++) {
                const int t = lane + 32 * u;
                if (t < i) pp = fmaf(cj[u], s_cis[row_l][t], pp);
            }
            const float scale = __fmul_rn(relj, rel_r[r]);
            num[r] = fmaf(scale, dp[r], -pp);
        }

        // interleaved butterfly: 20 independent SHFL+ADD pairs, pipelined
        #pragma unroll
        for (int off = 16; off; off >>= 1) {
            #pragma unroll
            for (int r = 0; r < RPW; r++)
                num[r] += __shfl_xor_sync(0xFFFFFFFFu, num[r], off);
        }

        // epilogue (all lanes redundantly; lane0 stores)
        unsigned long long wbest = 0ULL;
        #pragma unroll
        for (int r = 0; r < RPW; r++) {
            const int n     = n0 + warp * RPW + r;
            const int row_l = warp * RPW + r;
            const float e   = __fdiv_rn(num[r], sqj);
            if (lane == 0) {
                s_cis[row_l][i] = e;
                g_cisT[(size_t)n * TOPK + i] = e;
            }
            float d = __fsub_rn(d_r[r], __fmul_rn(e, e));
            if (n == j) d = NEG_MASK_F;
            d_r[r] = d;
            const unsigned long long p = pack_key(d, n);
            if (p > wbest) wbest = p;
        }
        if (lane == 0) s_best[warp] = wbest;
        __syncthreads();
        if (warp == 0) {                           // warp-0 shuffle reduce + publish
            unsigned long long bb = s_best[lane & (NWARPS - 1)];
            #pragma unroll
            for (int off = 4; off; off >>= 1) {
                unsigned long long q = __shfl_xor_sync(0xFFFFFFFFu, bb, off);
                if (q > bb) bb = q;
            }
            if (lane == 0) st_rel(&g_best[i + 1][g][0], bb);  // release covers cis stores
        }
    }

    // ---------------- OUT copy (off the critical loop) ----------------
    __syncthreads();
    const int jj = s_js[g];                        // CTA g copies output row g
    ((float4*)(OUT + (size_t)g * D_DIM))[tid] =
        ((const float4*)(IF + (size_t)jj * D_DIM))[tid];
}

extern "C" void kernel_launch(void* const* d_in, const int* in_sizes, int n_in,
                              void* d_out, int out_size) {
    const float* IF  = (const float*)d_in[0];   // image_features (1,4096,1024) f32
    const float* ATT = (const float*)d_in[1];   // attention (1,4096) f32
    float* OUT = (float*)d_out;                 // (128, 1024) f32
    (void)in_sizes; (void)n_in; (void)out_size;
    cdpruner_kernel<<<G_CTAS, T_THREADS>>>(IF, ATT, OUT);
}

// round 9
// speedup vs baseline: 1.4985x; 1.3955x over previous
#include <cuda_runtime.h>
#include <cstdint>

#define N_TOK 4096
#define D_DIM 1024
#define TOPK 128
#define G_CTAS 128
#define T_THREADS 256
#define NWARPS (T_THREADS / 32)            // 8
#define ROWS_PER_CTA (N_TOK / G_CTAS)      // 32
#define RPW (ROWS_PER_CTA / NWARPS)        // 4
#define NEG_MASK_F (-1e30f)

// ---------------- persistent device scratch (no allocations) ----------------
__device__ __align__(16) float g_xn[(size_t)N_TOK * D_DIM];   // normalized features (16 MB)
__device__ __align__(16) float g_cisT[(size_t)N_TOK * TOPK];  // cis transposed [n][t] (2 MB)
__device__ float g_rel[N_TOK];
// per-step exchange line: [0]=win (max-reduced packed key), [1]=cnt; 128B padded
__device__ __align__(128) unsigned long long g_ex[TOPK][16];  // 16 KB
__device__ float g_attmin[G_CTAS];
__device__ float g_attmax[G_CTAS];
__device__ unsigned int g_bar_cnt = 0;                        // sense-reversing barrier
__device__ unsigned int g_bar_gen = 0;

// Order-preserving float->u32 key; low word = inverted index so on equal keys
// the SMALLEST index wins (matches jnp.argmax first-occurrence). Never zero.
__device__ __forceinline__ unsigned long long pack_key(float v, int idx) {
    unsigned b = __float_as_uint(v);
    unsigned key = (b & 0x80000000u) ? ~b : (b | 0x80000000u);
    return ((unsigned long long)key << 32) | (unsigned)(0xFFFFFFFFu - (unsigned)idx);
}

__device__ __forceinline__ void publish_key(unsigned long long* line, unsigned long long key) {
    // max-reduce the candidate, release everything, then count the arrival
    asm volatile("red.relaxed.gpu.global.max.u64 [%0], %1;" :: "l"(line), "l"(key) : "memory");
    asm volatile("fence.acq_rel.gpu;" ::: "memory");
    asm volatile("red.relaxed.gpu.global.add.u64 [%0], %1;" :: "l"(line + 1), "l"(1ULL) : "memory");
}

__device__ __forceinline__ unsigned long long poll_winner(const unsigned long long* line) {
    unsigned long long win, cnt;
    do {
        asm volatile("ld.volatile.global.v2.u64 {%0,%1}, [%2];"
                     : "=l"(win), "=l"(cnt) : "l"(line));
    } while (cnt < (unsigned long long)G_CTAS);
    asm volatile("fence.acq_rel.gpu;" ::: "memory");   // acquire edge
    return win;
}

__device__ __forceinline__ void st_smem_u64(uint32_t a, unsigned long long v) {
    asm volatile("st.volatile.shared.u64 [%0], %1;" :: "r"(a), "l"(v) : "memory");
}
__device__ __forceinline__ unsigned long long ld_smem_vol_u64(uint32_t a) {
    unsigned long long v;
    asm volatile("ld.volatile.shared.u64 %0, [%1];" : "=l"(v) : "r"(a));
    return v;
}

__global__ void __launch_bounds__(T_THREADS, 1)
cdpruner_kernel(const float* __restrict__ IF, const float* __restrict__ ATT,
                float* __restrict__ OUT)
{
    const int g    = blockIdx.x;
    const int tid  = threadIdx.x;
    const int warp = tid >> 5;
    const int lane = tid & 31;
    const int n0   = g * ROWS_PER_CTA;

    __shared__ float s_mm[2];
    __shared__ unsigned long long s_best[NWARPS];
    __shared__ unsigned long long s_winv[2];      // double-buffered winner broadcast
    __shared__ float s_cis[ROWS_PER_CTA][TOPK];   // 16 KB, own rows' cis
    __shared__ int s_js[TOPK];

    const uint32_t a_winv = (uint32_t)__cvta_generic_to_shared(&s_winv[0]);

    // ---------------- Phase A ----------------
    // zero this CTA's exchange line (one line per step, CTA g owns step g)
    if (tid < 16) g_ex[g][tid] = 0ULL;
    if (tid == 16) { s_winv[0] = 0ULL; s_winv[1] = 0ULL; }

    if (warp == 0) {                              // attention min/max partials
        float v = ATT[n0 + lane];
        float vmin = v, vmax = v;
        #pragma unroll
        for (int off = 16; off; off >>= 1) {
            vmin = fminf(vmin, __shfl_xor_sync(0xFFFFFFFFu, vmin, off));
            vmax = fmaxf(vmax, __shfl_xor_sync(0xFFFFFFFFu, vmax, off));
        }
        if (lane == 0) { g_attmin[g] = vmin; g_attmax[g] = vmax; }
    }

    // Normalize rows; KEEP the normalized slice in registers (xr); write g_xn
    // for cross-CTA row-j reads.
    float4 xr[RPW][8];
    float  dd_r[RPW];
    #pragma unroll
    for (int r = 0; r < RPW; r++) {
        const int n = n0 + warp * RPW + r;
        const float4* xp = (const float4*)(IF + (size_t)n * D_DIM);
        float ss = 0.f;
        #pragma unroll
        for (int u = 0; u < 8; u++) {
            xr[r][u] = xp[u * 32 + lane];
            ss = fmaf(xr[r][u].x, xr[r][u].x, ss);
            ss = fmaf(xr[r][u].y, xr[r][u].y, ss);
            ss = fmaf(xr[r][u].z, xr[r][u].z, ss);
            ss = fmaf(xr[r][u].w, xr[r][u].w, ss);
        }
        #pragma unroll
        for (int off = 16; off; off >>= 1) ss += __shfl_xor_sync(0xFFFFFFFFu, ss, off);
        const float norm = __fsqrt_rn(ss);
        float dd = 0.f;
        float4* op = (float4*)(g_xn + (size_t)n * D_DIM);
        #pragma unroll
        for (int u = 0; u < 8; u++) {
            float4 o;
            o.x = __fdiv_rn(xr[r][u].x, norm);
            o.y = __fdiv_rn(xr[r][u].y, norm);
            o.z = __fdiv_rn(xr[r][u].z, norm);
            o.w = __fdiv_rn(xr[r][u].w, norm);
            dd = fmaf(o.x, o.x, dd);
            dd = fmaf(o.y, o.y, dd);
            dd = fmaf(o.z, o.z, dd);
            dd = fmaf(o.w, o.w, dd);
            xr[r][u] = o;
            op[u * 32 + lane] = o;
        }
        #pragma unroll
        for (int off = 16; off; off >>= 1) dd += __shfl_xor_sync(0xFFFFFFFFu, dd, off);
        dd_r[r] = dd;
    }

    // ---- sense-reversing grid barrier (covers g_xn + g_ex zeroing) ----
    __syncthreads();
    if (tid == 0) {
        __threadfence();
        unsigned gen = *(volatile unsigned*)&g_bar_gen;
        if (atomicAdd(&g_bar_cnt, 1u) == G_CTAS - 1) {
            g_bar_cnt = 0u;
            __threadfence();
            atomicAdd(&g_bar_gen, 1u);
        } else {
            while (*(volatile unsigned*)&g_bar_gen == gen) { }
        }
        __threadfence();
    }
    __syncthreads();

    // global attention min/max (redundant per CTA)
    if (warp == 0) {
        float vmin = g_attmin[lane], vmax = g_attmax[lane];
        #pragma unroll
        for (int k = 1; k < G_CTAS / 32; k++) {
            vmin = fminf(vmin, g_attmin[lane + 32 * k]);
            vmax = fmaxf(vmax, g_attmax[lane + 32 * k]);
        }
        #pragma unroll
        for (int off = 16; off; off >>= 1) {
            vmin = fminf(vmin, __shfl_xor_sync(0xFFFFFFFFu, vmin, off));
            vmax = fmaxf(vmax, __shfl_xor_sync(0xFFFFFFFFu, vmax, off));
        }
        if (lane == 0) { s_mm[0] = vmin; s_mm[1] = vmax; }
    }
    __syncthreads();

    // rel + initial di2s per owned row
    const float rmin  = -s_mm[1];
    const float rmax  = -s_mm[0];
    const float denom = __fsub_rn(rmax, rmin);
    float rel_r[RPW], d_r[RPW];
    {
        unsigned long long wbest = 0ULL;
        #pragma unroll
        for (int r = 0; r < RPW; r++) {
            const int n = n0 + warp * RPW + r;
            const float relv = __fdiv_rn(__fadd_rn(__fsub_rn(-ATT[n], rmin), 1e-6f), denom);
            rel_r[r] = relv;
            if (lane == 0) g_rel[n] = relv;
            const float dval = __fmul_rn(__fmul_rn(relv, dd_r[r]), relv);
            d_r[r] = dval;
            const unsigned long long p = pack_key(dval, n);
            if (p > wbest) wbest = p;
        }
        if (lane == 0) s_best[warp] = wbest;
    }
    __syncthreads();
    if (warp == 0) {
        unsigned long long bb = s_best[lane & (NWARPS - 1)];
        #pragma unroll
        for (int off = 4; off; off >>= 1) {
            unsigned long long q = __shfl_xor_sync(0xFFFFFFFFu, bb, off);
            if (q > bb) bb = q;
        }
        if (lane == 0) publish_key(&g_ex[0][0], bb);
    }

    // ---------------- Phase B: 128 greedy steps ----------------
    for (int i = 0; i < TOPK; i++) {
        const int b = i & 1;

        // winner acquisition: warp0 polls the single exchange line; others spin smem
        unsigned long long w;
        if (warp == 0) {
            w = poll_winner(&g_ex[i][0]);          // all lanes get it (coalesced bcast)
            if (lane == 0) st_smem_u64(a_winv + (unsigned)b * 8u, w);
        } else {
            const uint32_t a = a_winv + (unsigned)b * 8u;
            do { w = ld_smem_vol_u64(a); } while (w == 0ULL);
        }
        // reset this parity slot for reuse at step i+2 (warp1, before its compute;
        // ordered vs warp0's i+2 write by the end-of-step barrier chain)
        if (warp == 1 && lane == 0) { /* reset after decode below */ }

        const unsigned key  = (unsigned)(w >> 32);
        const unsigned bits = (key & 0x80000000u) ? (key ^ 0x80000000u) : ~key;
        const float dj = __uint_as_float(bits);
        int j = (int)(0xFFFFFFFFu - (unsigned)(w & 0xFFFFFFFFu));
        j = (j < 0) ? 0 : ((j > N_TOK - 1) ? N_TOK - 1 : j);   // defensive clamp
        if (tid == 0) s_js[i] = j;                 // output copied after the loop

        if (i == TOPK - 1) break;

        const float sqj  = __fsqrt_rn(dj);
        const float relj = __ldg(&g_rel[j]);

        // per-warp register loads of xn[j] and cisT[j] (read-once lines)
        const float4* xjp = (const float4*)(g_xn + (size_t)j * D_DIM);
        float4 xj[8];
        #pragma unroll
        for (int u = 0; u < 8; u++) xj[u] = xjp[u * 32 + lane];
        float cj[4];
        #pragma unroll
        for (int u = 0; u < 4; u++) {
            const int t = lane + 32 * u;
            cj[u] = (t < i) ? __ldg(&g_cisT[(size_t)j * TOPK + t]) : 0.f;
        }

        // 4-row-interleaved dot (independent FMA chains)
        float dp[RPW] = {0.f, 0.f, 0.f, 0.f};
        #pragma unroll
        for (int u = 0; u < 8; u++) {
            #pragma unroll
            for (int r = 0; r < RPW; r++) {
                dp[r] = fmaf(xj[u].x, xr[r][u].x, dp[r]);
                dp[r] = fmaf(xj[u].y, xr[r][u].y, dp[r]);
                dp[r] = fmaf(xj[u].z, xr[r][u].z, dp[r]);
                dp[r] = fmaf(xj[u].w, xr[r][u].w, dp[r]);
            }
        }

        // projection + fuse: num_lane = relj*rel_n*dp_lane - pp_lane
        float num[RPW];
        #pragma unroll
        for (int r = 0; r < RPW; r++) {
            const int row_l = warp * RPW + r;
            float pp = 0.f;
            #pragma unroll
            for (int u = 0; u < 4; u++) {
                const int t = lane + 32 * u;
                if (t < i) pp = fmaf(cj[u], s_cis[row_l][t], pp);
            }
            const float scale = __fmul_rn(relj, rel_r[r]);
            num[r] = fmaf(scale, dp[r], -pp);
        }

        // interleaved butterfly (rows pipelined per level)
        #pragma unroll
        for (int off = 16; off; off >>= 1) {
            #pragma unroll
            for (int r = 0; r < RPW; r++)
                num[r] += __shfl_xor_sync(0xFFFFFFFFu, num[r], off);
        }

        // epilogue
        unsigned long long wbest = 0ULL;
        #pragma unroll
        for (int r = 0; r < RPW; r++) {
            const int n     = n0 + warp * RPW + r;
            const int row_l = warp * RPW + r;
            const float e   = __fdiv_rn(num[r], sqj);
            if (lane == 0) {
                s_cis[row_l][i] = e;
                g_cisT[(size_t)n * TOPK + i] = e;
            }
            float d = __fsub_rn(d_r[r], __fmul_rn(e, e));
            if (n == j) d = NEG_MASK_F;
            d_r[r] = d;
            const unsigned long long p = pack_key(d, n);
            if (p > wbest) wbest = p;
        }
        if (lane == 0) s_best[warp] = wbest;
        if (warp == 1 && lane == 0) st_smem_u64(a_winv + (unsigned)b * 8u, 0ULL);  // slot reset
        __syncthreads();
        if (warp == 0) {
            unsigned long long bb = s_best[lane & (NWARPS - 1)];
            #pragma unroll
            for (int off = 4; off; off >>= 1) {
                unsigned long long q = __shfl_xor_sync(0xFFFFFFFFu, bb, off);
                if (q > bb) bb = q;
            }
            if (lane == 0) publish_key(&g_ex[i + 1][0], bb);  // fence inside covers cis stores
        }
    }

    // ---------------- OUT copy (off the critical loop) ----------------
    __syncthreads();
    const int jj = s_js[g];                        // CTA g copies output row g
    ((float4*)(OUT + (size_t)g * D_DIM))[tid] =
        ((const float4*)(IF + (size_t)jj * D_DIM))[tid];
}

extern "C" void kernel_launch(void* const* d_in, const int* in_sizes, int n_in,
                              void* d_out, int out_size) {
    const float* IF  = (const float*)d_in[0];   // image_features (1,4096,1024) f32
    const float* ATT = (const float*)d_in[1];   // attention (1,4096) f32
    float* OUT = (float*)d_out;                 // (128, 1024) f32
    (void)in_sizes; (void)n_in; (void)out_size;
    cdpruner_kernel<<<G_CTAS, T_THREADS>>>(IF, ATT, OUT);
}

// round 10
// speedup vs baseline: 1.7546x; 1.1709x over previous
#include <cuda_runtime.h>
#include <cstdint>

#define N_TOK 4096
#define D_DIM 1024
#define TOPK 128
#define G_CTAS 128
#define T_THREADS 256
#define NWARPS (T_THREADS / 32)            // 8
#define ROWS_PER_CTA (N_TOK / G_CTAS)      // 32
#define RPW (ROWS_PER_CTA / NWARPS)        // 4
#define NEG_MASK_F (-1e30f)

// ---------------- persistent device scratch (no allocations) ----------------
__device__ __align__(16) float g_xn[(size_t)N_TOK * D_DIM];   // normalized features (16 MB)
__device__ __align__(16) float g_cisT[(size_t)N_TOK * TOPK];  // cis transposed [n][t] (2 MB)
__device__ float g_rel[N_TOK];
// per-step exchange line: [0]=win (max-reduced packed key), [1]=cnt; 128B padded
__device__ __align__(128) unsigned long long g_ex[TOPK][16];  // 16 KB
__device__ float g_attmin[G_CTAS];
__device__ float g_attmax[G_CTAS];
__device__ unsigned int g_bar_cnt = 0;                        // sense-reversing barrier
__device__ unsigned int g_bar_gen = 0;

// Order-preserving float->u32 key; low word = inverted index so on equal keys
// the SMALLEST index wins (matches jnp.argmax first-occurrence). Never zero.
__device__ __forceinline__ unsigned long long pack_key(float v, int idx) {
    unsigned b = __float_as_uint(v);
    unsigned key = (b & 0x80000000u) ? ~b : (b | 0x80000000u);
    return ((unsigned long long)key << 32) | (unsigned)(0xFFFFFFFFu - (unsigned)idx);
}

// Publish: relaxed max-reduce of candidate, then RELEASE count-increment.
// The release on the add orders this CTA's prior g_cisT stores (sequenced by the
// preceding __syncthreads) before the count becomes visible -> any consumer that
// observes cnt==128 sees all cis data in L2. Consumers read only never-before-
// touched lines (row selected once), so no consumer-side fence is required.
__device__ __forceinline__ void publish_key(unsigned long long* line, unsigned long long key) {
    asm volatile("red.relaxed.gpu.global.max.u64 [%0], %1;" :: "l"(line), "l"(key) : "memory");
    asm volatile("red.release.gpu.global.add.u64 [%0], %1;" :: "l"(line + 1), "l"(1ULL) : "memory");
}

__device__ __forceinline__ unsigned long long poll_winner(const unsigned long long* line) {
    unsigned long long win, cnt;
    do {
        asm volatile("ld.volatile.global.v2.u64 {%0,%1}, [%2];"
                     : "=l"(win), "=l"(cnt) : "l"(line));
    } while (cnt < (unsigned long long)G_CTAS);
    return win;                                    // no fence: read-once-line consumers
}

__device__ __forceinline__ void st_smem_u64(uint32_t a, unsigned long long v) {
    asm volatile("st.volatile.shared.u64 [%0], %1;" :: "r"(a), "l"(v) : "memory");
}
__device__ __forceinline__ unsigned long long ld_smem_vol_u64(uint32_t a) {
    unsigned long long v;
    asm volatile("ld.volatile.shared.u64 %0, [%1];" : "=l"(v) : "r"(a));
    return v;
}

__global__ void __launch_bounds__(T_THREADS, 1)
cdpruner_kernel(const float* __restrict__ IF, const float* __restrict__ ATT,
                float* __restrict__ OUT)
{
    const int g    = blockIdx.x;
    const int tid  = threadIdx.x;
    const int warp = tid >> 5;
    const int lane = tid & 31;
    const int n0   = g * ROWS_PER_CTA;

    __shared__ float s_mm[2];
    __shared__ unsigned long long s_best[NWARPS];
    __shared__ unsigned long long s_winv[2];      // double-buffered winner broadcast
    __shared__ float s_cis[ROWS_PER_CTA][TOPK];   // 16 KB, own rows' cis
    __shared__ int s_js[TOPK];

    const uint32_t a_winv = (uint32_t)__cvta_generic_to_shared(&s_winv[0]);

    // ---------------- Phase A ----------------
    if (tid < 16) g_ex[g][tid] = 0ULL;            // zero this CTA's exchange line
    if (tid == 16) { s_winv[0] = 0ULL; s_winv[1] = 0ULL; }

    if (warp == 0) {                              // attention min/max partials
        float v = ATT[n0 + lane];
        float vmin = v, vmax = v;
        #pragma unroll
        for (int off = 16; off; off >>= 1) {
            vmin = fminf(vmin, __shfl_xor_sync(0xFFFFFFFFu, vmin, off));
            vmax = fmaxf(vmax, __shfl_xor_sync(0xFFFFFFFFu, vmax, off));
        }
        if (lane == 0) { g_attmin[g] = vmin; g_attmax[g] = vmax; }
    }

    // Normalize rows; KEEP the normalized slice in registers (xr); write g_xn
    // for cross-CTA row-j reads.
    float4 xr[RPW][8];
    float  dd_r[RPW];
    #pragma unroll
    for (int r = 0; r < RPW; r++) {
        const int n = n0 + warp * RPW + r;
        const float4* xp = (const float4*)(IF + (size_t)n * D_DIM);
        float ss = 0.f;
        #pragma unroll
        for (int u = 0; u < 8; u++) {
            xr[r][u] = xp[u * 32 + lane];
            ss = fmaf(xr[r][u].x, xr[r][u].x, ss);
            ss = fmaf(xr[r][u].y, xr[r][u].y, ss);
            ss = fmaf(xr[r][u].z, xr[r][u].z, ss);
            ss = fmaf(xr[r][u].w, xr[r][u].w, ss);
        }
        #pragma unroll
        for (int off = 16; off; off >>= 1) ss += __shfl_xor_sync(0xFFFFFFFFu, ss, off);
        const float norm = __fsqrt_rn(ss);
        float dd = 0.f;
        float4* op = (float4*)(g_xn + (size_t)n * D_DIM);
        #pragma unroll
        for (int u = 0; u < 8; u++) {
            float4 o;
            o.x = __fdiv_rn(xr[r][u].x, norm);
            o.y = __fdiv_rn(xr[r][u].y, norm);
            o.z = __fdiv_rn(xr[r][u].z, norm);
            o.w = __fdiv_rn(xr[r][u].w, norm);
            dd = fmaf(o.x, o.x, dd);
            dd = fmaf(o.y, o.y, dd);
            dd = fmaf(o.z, o.z, dd);
            dd = fmaf(o.w, o.w, dd);
            xr[r][u] = o;
            op[u * 32 + lane] = o;
        }
        #pragma unroll
        for (int off = 16; off; off >>= 1) dd += __shfl_xor_sync(0xFFFFFFFFu, dd, off);
        dd_r[r] = dd;
    }

    // ---- sense-reversing grid barrier (covers g_xn + g_ex zeroing) ----
    __syncthreads();
    if (tid == 0) {
        __threadfence();
        unsigned gen = *(volatile unsigned*)&g_bar_gen;
        if (atomicAdd(&g_bar_cnt, 1u) == G_CTAS - 1) {
            g_bar_cnt = 0u;
            __threadfence();
            atomicAdd(&g_bar_gen, 1u);
        } else {
            while (*(volatile unsigned*)&g_bar_gen == gen) { }
        }
        __threadfence();
    }
    __syncthreads();

    // global attention min/max (redundant per CTA)
    if (warp == 0) {
        float vmin = g_attmin[lane], vmax = g_attmax[lane];
        #pragma unroll
        for (int k = 1; k < G_CTAS / 32; k++) {
            vmin = fminf(vmin, g_attmin[lane + 32 * k]);
            vmax = fmaxf(vmax, g_attmax[lane + 32 * k]);
        }
        #pragma unroll
        for (int off = 16; off; off >>= 1) {
            vmin = fminf(vmin, __shfl_xor_sync(0xFFFFFFFFu, vmin, off));
            vmax = fmaxf(vmax, __shfl_xor_sync(0xFFFFFFFFu, vmax, off));
        }
        if (lane == 0) { s_mm[0] = vmin; s_mm[1] = vmax; }
    }
    __syncthreads();

    // rel + initial di2s per owned row
    const float rmin  = -s_mm[1];
    const float rmax  = -s_mm[0];
    const float denom = __fsub_rn(rmax, rmin);
    float rel_r[RPW], d_r[RPW];
    {
        unsigned long long wbest = 0ULL;
        #pragma unroll
        for (int r = 0; r < RPW; r++) {
            const int n = n0 + warp * RPW + r;
            const float relv = __fdiv_rn(__fadd_rn(__fsub_rn(-ATT[n], rmin), 1e-6f), denom);
            rel_r[r] = relv;
            if (lane == 0) g_rel[n] = relv;
            const float dval = __fmul_rn(__fmul_rn(relv, dd_r[r]), relv);
            d_r[r] = dval;
            const unsigned long long p = pack_key(dval, n);
            if (p > wbest) wbest = p;
        }
        if (lane == 0) s_best[warp] = wbest;
    }
    __syncthreads();
    if (warp == 0) {
        unsigned long long bb = s_best[lane & (NWARPS - 1)];
        #pragma unroll
        for (int off = 4; off; off >>= 1) {
            unsigned long long q = __shfl_xor_sync(0xFFFFFFFFu, bb, off);
            if (q > bb) bb = q;
        }
        if (lane == 0) publish_key(&g_ex[0][0], bb);
    }

    // ---------------- Phase B: 128 greedy steps ----------------
    for (int i = 0; i < TOPK; i++) {
        const int b = i & 1;

        // winner acquisition: warp0 polls the exchange line, relays IMMEDIATELY;
        // other warps spin on local smem (no L2 traffic, no fences)
        unsigned long long w;
        if (warp == 0) {
            w = poll_winner(&g_ex[i][0]);
            if (lane == 0) st_smem_u64(a_winv + (unsigned)b * 8u, w);
        } else {
            const uint32_t a = a_winv + (unsigned)b * 8u;
            do { w = ld_smem_vol_u64(a); } while (w == 0ULL);
        }

        const unsigned key  = (unsigned)(w >> 32);
        const unsigned bits = (key & 0x80000000u) ? (key ^ 0x80000000u) : ~key;
        const float dj = __uint_as_float(bits);
        int j = (int)(0xFFFFFFFFu - (unsigned)(w & 0xFFFFFFFFu));
        j &= (N_TOK - 1);                          // defensive mask (power of two)
        if (tid == 0) s_js[i] = j;                 // output copied after the loop

        if (i == TOPK - 1) break;

        const float sqj  = __fsqrt_rn(dj);
        const float relj = __ldg(&g_rel[j]);

        // per-warp register loads of xn[j] and cisT[j] (read-once lines)
        const float4* xjp = (const float4*)(g_xn + (size_t)j * D_DIM);
        float4 xj[8];
        #pragma unroll
        for (int u = 0; u < 8; u++) xj[u] = xjp[u * 32 + lane];
        float cj[4];
        #pragma unroll
        for (int u = 0; u < 4; u++) {
            const int t = lane + 32 * u;
            cj[u] = (t < i) ? __ldg(&g_cisT[(size_t)j * TOPK + t]) : 0.f;
        }

        // 4-row-interleaved dot (independent FMA chains)
        float dp[RPW] = {0.f, 0.f, 0.f, 0.f};
        #pragma unroll
        for (int u = 0; u < 8; u++) {
            #pragma unroll
            for (int r = 0; r < RPW; r++) {
                dp[r] = fmaf(xj[u].x, xr[r][u].x, dp[r]);
                dp[r] = fmaf(xj[u].y, xr[r][u].y, dp[r]);
                dp[r] = fmaf(xj[u].z, xr[r][u].z, dp[r]);
                dp[r] = fmaf(xj[u].w, xr[r][u].w, dp[r]);
            }
        }

        // projection + fuse: num_lane = relj*rel_n*dp_lane - pp_lane
        float num[RPW];
        #pragma unroll
        for (int r = 0; r < RPW; r++) {
            const int row_l = warp * RPW + r;
            float pp = 0.f;
            #pragma unroll
            for (int u = 0; u < 4; u++) {
                const int t = lane + 32 * u;
                if (t < i) pp = fmaf(cj[u], s_cis[row_l][t], pp);
            }
            const float scale = __fmul_rn(relj, rel_r[r]);
            num[r] = fmaf(scale, dp[r], -pp);
        }

        // interleaved butterfly (rows pipelined per level)
        #pragma unroll
        for (int off = 16; off; off >>= 1) {
            #pragma unroll
            for (int r = 0; r < RPW; r++)
                num[r] += __shfl_xor_sync(0xFFFFFFFFu, num[r], off);
        }

        // epilogue
        unsigned long long wbest = 0ULL;
        #pragma unroll
        for (int r = 0; r < RPW; r++) {
            const int n     = n0 + warp * RPW + r;
            const int row_l = warp * RPW + r;
            const float e   = __fdiv_rn(num[r], sqj);
            if (lane == 0) {
                s_cis[row_l][i] = e;
                g_cisT[(size_t)n * TOPK + i] = e;
            }
            float d = __fsub_rn(d_r[r], __fmul_rn(e, e));
            if (n == j) d = NEG_MASK_F;
            d_r[r] = d;
            const unsigned long long p = pack_key(d, n);
            if (p > wbest) wbest = p;
        }
        if (lane == 0) s_best[warp] = wbest;
        if (warp == 1 && lane == 0) st_smem_u64(a_winv + (unsigned)b * 8u, 0ULL);  // slot reset
        __syncthreads();
        if (warp == 0) {
            unsigned long long bb = s_best[lane & (NWARPS - 1)];
            #pragma unroll
            for (int off = 4; off; off >>= 1) {
                unsigned long long q = __shfl_xor_sync(0xFFFFFFFFu, bb, off);
                if (q > bb) bb = q;
            }
            if (lane == 0) publish_key(&g_ex[i + 1][0], bb);  // release-add covers cis stores
        }
    }

    // ---------------- OUT copy (off the critical loop) ----------------
    __syncthreads();
    const int jj = s_js[g];                        // CTA g copies output row g
    ((float4*)(OUT + (size_t)g * D_DIM))[tid] =
        ((const float4*)(IF + (size_t)jj * D_DIM))[tid];
}

extern "C" void kernel_launch(void* const* d_in, const int* in_sizes, int n_in,
                              void* d_out, int out_size) {
    const float* IF  = (const float*)d_in[0];   // image_features (1,4096,1024) f32
    const float* ATT = (const float*)d_in[1];   // attention (1,4096) f32
    float* OUT = (float*)d_out;                 // (128, 1024) f32
    (void)in_sizes; (void)n_in; (void)out_size;
    cdpruner_kernel<<<G_CTAS, T_THREADS>>>(IF, ATT, OUT);
}